// round 1
// baseline (speedup 1.0000x reference)
#include <cuda_runtime.h>
#include <cuda_bf16.h>
#include <cstdint>

// Problem constants (fixed by the dataset)
#define NNODES 100000
#define NREL   8
#define F      128

// Scratch: __device__ globals (no allocation allowed)
__device__ __align__(16) float        g_proj[(size_t)NREL * NNODES * F]; // 409.6 MB
__device__ __align__(16) __nv_bfloat16 g_fh[(size_t)NNODES * F];
__device__ __align__(16) __nv_bfloat16 g_fl[(size_t)NNODES * F];
__device__ __align__(16) __nv_bfloat16 g_wh[NREL * F * F];
__device__ __align__(16) __nv_bfloat16 g_wl[NREL * F * F];

// ---------------------------------------------------------------------------
// Split fp32 -> bf16 hi + bf16 lo (Markidis-style error compensation inputs)
// ---------------------------------------------------------------------------
__global__ void split_feat_kernel(const float* __restrict__ x, int n) {
    int i = blockIdx.x * blockDim.x + threadIdx.x;
    if (i < n) {
        float v = x[i];
        __nv_bfloat16 h = __float2bfloat16(v);
        g_fh[i] = h;
        g_fl[i] = __float2bfloat16(v - __bfloat162float(h));
    }
}

__global__ void split_w_kernel(const float* __restrict__ x, int n) {
    int i = blockIdx.x * blockDim.x + threadIdx.x;
    if (i < n) {
        float v = x[i];
        __nv_bfloat16 h = __float2bfloat16(v);
        g_wh[i] = h;
        g_wl[i] = __float2bfloat16(v - __bfloat162float(h));
    }
}

// ---------------------------------------------------------------------------
// GEMM: proj[r] = feat @ W_r using mma.sync m16n8k16 bf16, 3-term split.
// Block = 128x128 C tile, K=128 in one shot. 256 threads = 8 warps (4x2),
// each warp does a 32x64 subtile.
// ---------------------------------------------------------------------------
#define PITCH 136  // bf16 elems per smem row; (g*68 + tg) % 32 conflict-free

__device__ __forceinline__ void mma16816(float c[4], const uint32_t a[4],
                                         const uint32_t b[2]) {
    asm volatile(
        "mma.sync.aligned.m16n8k16.row.col.f32.bf16.bf16.f32 "
        "{%0,%1,%2,%3}, {%4,%5,%6,%7}, {%8,%9}, {%0,%1,%2,%3};"
        : "+f"(c[0]), "+f"(c[1]), "+f"(c[2]), "+f"(c[3])
        : "r"(a[0]), "r"(a[1]), "r"(a[2]), "r"(a[3]), "r"(b[0]), "r"(b[1]));
}

__global__ void __launch_bounds__(256) gemm_kernel(int n_nodes) {
    extern __shared__ __nv_bfloat16 sm[];
    __nv_bfloat16* Ah = sm;
    __nv_bfloat16* Al = Ah + 128 * PITCH;
    __nv_bfloat16* Bh = Al + 128 * PITCH;  // W transposed: [n][k]
    __nv_bfloat16* Bl = Bh + 128 * PITCH;

    const int r   = blockIdx.y;
    const int m0  = blockIdx.x * 128;
    const int tid = threadIdx.x;

    // Load A tile (hi+lo) as uint2 (4 bf16 per load), zero-fill OOB rows.
    {
        const uint2* fh = reinterpret_cast<const uint2*>(g_fh);
        const uint2* fl = reinterpret_cast<const uint2*>(g_fl);
        for (int i = tid; i < 128 * 32; i += 256) {
            int row = i >> 5, c4 = i & 31;
            uint2 vh = make_uint2(0u, 0u), vl = make_uint2(0u, 0u);
            int m = m0 + row;
            if (m < n_nodes) {
                vh = fh[(size_t)m * 32 + c4];
                vl = fl[(size_t)m * 32 + c4];
            }
            *reinterpret_cast<uint2*>(&Ah[row * PITCH + c4 * 4]) = vh;
            *reinterpret_cast<uint2*>(&Al[row * PITCH + c4 * 4]) = vl;
        }
    }
    // Load W_r transposed into smem: Bs[n][k]
    {
        const __nv_bfloat16* wh = g_wh + (size_t)r * F * F;
        const __nv_bfloat16* wl = g_wl + (size_t)r * F * F;
        for (int i = tid; i < F * F; i += 256) {
            int k = i >> 7, n = i & 127;
            Bh[n * PITCH + k] = wh[i];
            Bl[n * PITCH + k] = wl[i];
        }
    }
    __syncthreads();

    const int wid = tid >> 5, lane = tid & 31;
    const int g = lane >> 2, tg = lane & 3;
    const int wm = (wid & 3) * 32;   // warp row base within tile
    const int wn = (wid >> 2) * 64;  // warp col base within tile

    float acc[2][8][4];
#pragma unroll
    for (int a = 0; a < 2; a++)
#pragma unroll
        for (int b = 0; b < 8; b++)
#pragma unroll
            for (int c = 0; c < 4; c++) acc[a][b][c] = 0.f;

#pragma unroll
    for (int kk = 0; kk < 8; kk++) {
        const int k0 = kk * 16;
        uint32_t ah[2][4], al[2][4];
#pragma unroll
        for (int mi = 0; mi < 2; mi++) {
            const int rA = wm + mi * 16;
            ah[mi][0] = *(const uint32_t*)&Ah[(rA + g) * PITCH + k0 + 2 * tg];
            ah[mi][1] = *(const uint32_t*)&Ah[(rA + g + 8) * PITCH + k0 + 2 * tg];
            ah[mi][2] = *(const uint32_t*)&Ah[(rA + g) * PITCH + k0 + 2 * tg + 8];
            ah[mi][3] = *(const uint32_t*)&Ah[(rA + g + 8) * PITCH + k0 + 2 * tg + 8];
            al[mi][0] = *(const uint32_t*)&Al[(rA + g) * PITCH + k0 + 2 * tg];
            al[mi][1] = *(const uint32_t*)&Al[(rA + g + 8) * PITCH + k0 + 2 * tg];
            al[mi][2] = *(const uint32_t*)&Al[(rA + g) * PITCH + k0 + 2 * tg + 8];
            al[mi][3] = *(const uint32_t*)&Al[(rA + g + 8) * PITCH + k0 + 2 * tg + 8];
        }
#pragma unroll
        for (int ni = 0; ni < 8; ni++) {
            const int nb = wn + ni * 8;
            uint32_t bh[2], bl[2];
            bh[0] = *(const uint32_t*)&Bh[(nb + g) * PITCH + k0 + 2 * tg];
            bh[1] = *(const uint32_t*)&Bh[(nb + g) * PITCH + k0 + 2 * tg + 8];
            bl[0] = *(const uint32_t*)&Bl[(nb + g) * PITCH + k0 + 2 * tg];
            bl[1] = *(const uint32_t*)&Bl[(nb + g) * PITCH + k0 + 2 * tg + 8];
#pragma unroll
            for (int mi = 0; mi < 2; mi++) {
                mma16816(acc[mi][ni], ah[mi], bh);  // hi*hi
                mma16816(acc[mi][ni], al[mi], bh);  // lo*hi
                mma16816(acc[mi][ni], ah[mi], bl);  // hi*lo
            }
        }
    }

    // Store C tile
    float* cp = g_proj + ((size_t)r * n_nodes + m0) * F;
#pragma unroll
    for (int mi = 0; mi < 2; mi++) {
        const int r0 = wm + mi * 16 + g;
        const int r1 = r0 + 8;
#pragma unroll
        for (int ni = 0; ni < 8; ni++) {
            const int col = wn + ni * 8 + 2 * tg;
            if (m0 + r0 < n_nodes) {
                cp[(size_t)r0 * F + col]     = acc[mi][ni][0];
                cp[(size_t)r0 * F + col + 1] = acc[mi][ni][1];
            }
            if (m0 + r1 < n_nodes) {
                cp[(size_t)r1 * F + col]     = acc[mi][ni][2];
                cp[(size_t)r1 * F + col + 1] = acc[mi][ni][3];
            }
        }
    }
}

// ---------------------------------------------------------------------------
// Scatter: one warp per edge. 32 lanes x float4 = 128 floats gathered from
// proj[etype][src], vector-reduced into out[dst] (out fits in L2).
// ---------------------------------------------------------------------------
__global__ void scatter_kernel(const int* __restrict__ src,
                               const int* __restrict__ dst,
                               const int* __restrict__ et,
                               float* __restrict__ out, int E, int n_nodes) {
    int w = (blockIdx.x * blockDim.x + threadIdx.x) >> 5;
    int lane = threadIdx.x & 31;
    if (w >= E) return;
    int s = src[w];
    int d = dst[w];
    int r = et[w];
    const float4* p = reinterpret_cast<const float4*>(
        g_proj + ((size_t)r * n_nodes + s) * F);
    float4 v = p[lane];
    float* o = out + (size_t)d * F + lane * 4;
    asm volatile("red.global.add.v4.f32 [%0], {%1,%2,%3,%4};"
                 :: "l"(o), "f"(v.x), "f"(v.y), "f"(v.z), "f"(v.w)
                 : "memory");
}

// ---------------------------------------------------------------------------
extern "C" void kernel_launch(void* const* d_in, const int* in_sizes, int n_in,
                              void* d_out, int out_size) {
    const float* feat   = (const float*)d_in[0];
    const float* weight = (const float*)d_in[1];
    const int*   src    = (const int*)d_in[2];
    const int*   dst    = (const int*)d_in[3];
    const int*   et     = (const int*)d_in[4];

    const int n_nodes = in_sizes[0] / F;   // 100000
    const int n_w     = in_sizes[1];       // 8*128*128
    const int E       = in_sizes[2];       // 1.6M
    float* out = (float*)d_out;

    // 1) Split inputs into bf16 hi/lo
    split_feat_kernel<<<(n_nodes * F + 255) / 256, 256>>>(feat, n_nodes * F);
    split_w_kernel<<<(n_w + 255) / 256, 256>>>(weight, n_w);

    // 2) Dense projection GEMMs (8 relations)
    const int smem_bytes = 4 * 128 * PITCH * (int)sizeof(__nv_bfloat16); // 139264
    cudaFuncSetAttribute(gemm_kernel,
                         cudaFuncAttributeMaxDynamicSharedMemorySize, smem_bytes);
    dim3 ggrid((n_nodes + 127) / 128, NREL);
    gemm_kernel<<<ggrid, 256, smem_bytes>>>(n_nodes);

    // 3) Zero output (poisoned by harness), then edge scatter
    cudaMemsetAsync(d_out, 0, (size_t)out_size * sizeof(float));
    scatter_kernel<<<(E + 7) / 8, 256>>>(src, dst, et, out, E, n_nodes);
}

// round 4
// speedup vs baseline: 1.7258x; 1.7258x over previous
#include <cuda_runtime.h>
#include <cuda_bf16.h>
#include <cstdint>

#define NREL 8
#define F    128
#define NMAX 100000

// Scratch (no allocation allowed)
__device__ __align__(16) float         g_proj[(size_t)NREL * NMAX * F]; // 409.6 MB
__device__ __align__(16) __nv_bfloat16 g_fh[(size_t)NMAX * F];
__device__ __align__(16) __nv_bfloat16 g_fl[(size_t)NMAX * F];
__device__ __align__(16) __nv_bfloat16 g_wh[NREL * F * F];  // transposed: [r][n][k]
__device__ __align__(16) __nv_bfloat16 g_wl[NREL * F * F];  // transposed: [r][n][k]

// ---------------------------------------------------------------------------
// fp32 -> bf16 hi/lo splits
// ---------------------------------------------------------------------------
__global__ void split_feat_kernel(const float* __restrict__ x, int n) {
    int i = blockIdx.x * blockDim.x + threadIdx.x;
    if (i < n) {
        float v = x[i];
        __nv_bfloat16 h = __float2bfloat16(v);
        g_fh[i] = h;
        g_fl[i] = __float2bfloat16(v - __bfloat162float(h));
    }
}

// weight [r][k][n] fp32 -> transposed bf16 hi/lo [r][n][k]
__global__ void split_w_kernel(const float* __restrict__ x, int n) {
    int i = blockIdx.x * blockDim.x + threadIdx.x;
    if (i < n) {
        int r = i >> 14, rem = i & 16383, k = rem >> 7, nn = rem & 127;
        float v = x[i];
        __nv_bfloat16 h = __float2bfloat16(v);
        int o = r * 16384 + nn * 128 + k;
        g_wh[o] = h;
        g_wl[o] = __float2bfloat16(v - __bfloat162float(h));
    }
}

// ---------------------------------------------------------------------------
// Legacy-pipe GEMM building blocks
// ---------------------------------------------------------------------------
__device__ __forceinline__ uint32_t smem_u32(const void* p) {
    uint32_t a;
    asm("{ .reg .u64 t; cvta.to.shared.u64 t, %1; cvt.u32.u64 %0, t; }" : "=r"(a) : "l"(p));
    return a;
}

__device__ __forceinline__ void mma16816(float c[4], const uint32_t a[4],
                                         const uint32_t b0, const uint32_t b1) {
    asm volatile(
        "mma.sync.aligned.m16n8k16.row.col.f32.bf16.bf16.f32 "
        "{%0,%1,%2,%3}, {%4,%5,%6,%7}, {%8,%9}, {%0,%1,%2,%3};"
        : "+f"(c[0]), "+f"(c[1]), "+f"(c[2]), "+f"(c[3])
        : "r"(a[0]), "r"(a[1]), "r"(a[2]), "r"(a[3]), "r"(b0), "r"(b1));
}

#define LDSM_X4(r, addr) \
    asm volatile("ldmatrix.sync.aligned.m8n8.x4.shared.b16 {%0,%1,%2,%3}, [%4];" \
                 : "=r"((r)[0]), "=r"((r)[1]), "=r"((r)[2]), "=r"((r)[3]) : "r"(addr))

// Tile layout in smem: 128 rows, pitch 272 B (136 bf16). Row stride = 68 elems
// mod 32 banks = 4 -> any 8 consecutive rows cover all 32 banks: LDSM conflict-free.
#define PITCH_B 272
#define TILE_SZ (128 * PITCH_B)   // 34816 B

// cp.async one 128x128 bf16 tile (gmem row-major 256 B/row) into pitched smem.
// 2048 16-B chunks; rows >= valid zero-filled via src-size 0.
__device__ __forceinline__ void cpa_tile(uint32_t s_base, const __nv_bfloat16* g,
                                         int valid_rows, int tid) {
    const char* gc = reinterpret_cast<const char*>(g);
#pragma unroll
    for (int it = 0; it < 4; it++) {
        int i = tid + it * 512;
        int m = i >> 4, c = i & 15;
        uint32_t s = s_base + m * PITCH_B + c * 16;
        const char* src = gc + m * 256 + c * 16;
        int sz = (m < valid_rows) ? 16 : 0;
        asm volatile("cp.async.cg.shared.global [%0], [%1], 16, %2;"
                     :: "r"(s), "l"(src), "r"(sz) : "memory");
    }
}

// SMEM map: A-hi 0, A-lo 34816, B buf0 69632 (hi; lo at +34816), buf1 139264
#define OFF_AH 0u
#define OFF_AL 34816u
#define OFF_B0 69632u
#define OFF_B1 139264u
#define SMEM_SZ 208896

// ---------------------------------------------------------------------------
// GEMM: per CTA one 128-row M-tile, loop 8 relations.
// 512 threads = 16 warps (8 m-blocks x 2 n-halves), warp tile 16x64.
// 3-term bf16 split: hi*hi + lo*hi + hi*lo, fp32 accumulate.
// ---------------------------------------------------------------------------
__global__ void __launch_bounds__(512, 1) gemm_kernel(int n_nodes) {
    extern __shared__ __align__(128) char smem[];
    const uint32_t sb = smem_u32(smem);
    const int tid = threadIdx.x, wid = tid >> 5, lane = tid & 31;
    const int m0 = blockIdx.x * 128;
    const int valid = n_nodes - m0;  // may exceed 128

    // Stage A (hi+lo) and relation-0 B (hi+lo)
    cpa_tile(sb + OFF_AH, g_fh + (size_t)m0 * F, valid, tid);
    cpa_tile(sb + OFF_AL, g_fl + (size_t)m0 * F, valid, tid);
    cpa_tile(sb + OFF_B0,           g_wh, 128, tid);
    cpa_tile(sb + OFF_B0 + TILE_SZ, g_wl, 128, tid);
    asm volatile("cp.async.commit_group;" ::: "memory");
    asm volatile("cp.async.wait_group 0;" ::: "memory");
    __syncthreads();

    const int wm = (wid >> 1) * 16;   // warp m base
    const int wn = (wid & 1) * 64;    // warp n base

    // ldmatrix address components
    // A (x4): lanes 0-15 -> rows wm+0..15 at k0; lanes 16-31 -> same rows at k0+8
    const uint32_t a_off =
        (uint32_t)((wm + (lane & 15)) * PITCH_B + ((lane >> 4) * 8) * 2);
    // B (x4, NON-trans): matrix0=(n0-7,k0-7) m1=(n8-15,k0-7) m2=(n0-7,k8-15) m3=(n8-15,k8-15)
    const int b_row = (lane & 7) + ((lane >> 3) & 1) * 8;   // n row within 16-block
    const uint32_t b_koff = (uint32_t)(((lane >> 4) * 8) * 2);

    const int r0 = wm + (lane >> 2);
    const bool ok0 = (m0 + r0) < n_nodes;
    const bool ok1 = (m0 + r0 + 8) < n_nodes;

    for (int q = 0; q < NREL; q++) {
        const uint32_t bb = sb + ((q & 1) ? OFF_B1 : OFF_B0);
        if (q < 7) {  // prefetch next relation's B into the other buffer
            const uint32_t nb_ = sb + (((q + 1) & 1) ? OFF_B1 : OFF_B0);
            cpa_tile(nb_,           g_wh + (size_t)(q + 1) * F * F, 128, tid);
            cpa_tile(nb_ + TILE_SZ, g_wl + (size_t)(q + 1) * F * F, 128, tid);
            asm volatile("cp.async.commit_group;" ::: "memory");
        }

        float acc[8][4];
#pragma unroll
        for (int i = 0; i < 8; i++)
#pragma unroll
            for (int j = 0; j < 4; j++) acc[i][j] = 0.f;

#pragma unroll
        for (int kk = 0; kk < 8; kk++) {
            const uint32_t k2 = (uint32_t)(kk * 32);  // k0*2 bytes
            uint32_t ah[4], al[4];
            LDSM_X4(ah, sb + OFF_AH + a_off + k2);
            LDSM_X4(al, sb + OFF_AL + a_off + k2);
#pragma unroll
            for (int nb = 0; nb < 4; nb++) {
                const uint32_t baddr =
                    bb + (uint32_t)((wn + nb * 16 + b_row) * PITCH_B) + b_koff + k2;
                uint32_t bh[4], bl[4];
                LDSM_X4(bh, baddr);            // non-trans: k-contiguous pairs at fixed n
                LDSM_X4(bl, baddr + TILE_SZ);
                float* a0 = acc[nb * 2];
                float* a1 = acc[nb * 2 + 1];
                // interleave the two n-subtiles to break same-acc dep chains
                mma16816(a0, ah, bh[0], bh[2]);
                mma16816(a1, ah, bh[1], bh[3]);
                mma16816(a0, al, bh[0], bh[2]);
                mma16816(a1, al, bh[1], bh[3]);
                mma16816(a0, ah, bl[0], bl[2]);
                mma16816(a1, ah, bl[1], bl[3]);
            }
        }

        // store C tile for relation q
        float* cp = g_proj + ((size_t)q * n_nodes + m0) * F;
#pragma unroll
        for (int ns = 0; ns < 8; ns++) {
            const int col = wn + ns * 8 + (lane & 3) * 2;
            if (ok0) *(float2*)&cp[(size_t)r0 * F + col] =
                make_float2(acc[ns][0], acc[ns][1]);
            if (ok1) *(float2*)&cp[(size_t)(r0 + 8) * F + col] =
                make_float2(acc[ns][2], acc[ns][3]);
        }

        if (q < 7) {
            asm volatile("cp.async.wait_group 0;" ::: "memory");
            __syncthreads();
        }
    }
}

// ---------------------------------------------------------------------------
// Scatter: one warp per edge, red.global.add.v4.f32 into L2-resident out
// ---------------------------------------------------------------------------
__global__ void scatter_kernel(const int* __restrict__ src,
                               const int* __restrict__ dst,
                               const int* __restrict__ et,
                               float* __restrict__ out, int E, int n_nodes) {
    int w = (blockIdx.x * blockDim.x + threadIdx.x) >> 5;
    int lane = threadIdx.x & 31;
    if (w >= E) return;
    int s = src[w];
    int d = dst[w];
    int r = et[w];
    const float4* p = reinterpret_cast<const float4*>(
        g_proj + ((size_t)r * n_nodes + s) * F);
    float4 v = p[lane];
    float* o = out + (size_t)d * F + lane * 4;
    asm volatile("red.global.add.v4.f32 [%0], {%1,%2,%3,%4};"
                 :: "l"(o), "f"(v.x), "f"(v.y), "f"(v.z), "f"(v.w) : "memory");
}

// ---------------------------------------------------------------------------
extern "C" void kernel_launch(void* const* d_in, const int* in_sizes, int n_in,
                              void* d_out, int out_size) {
    const float* feat   = (const float*)d_in[0];
    const float* weight = (const float*)d_in[1];
    const int*   src    = (const int*)d_in[2];
    const int*   dst    = (const int*)d_in[3];
    const int*   et     = (const int*)d_in[4];

    const int n_nodes = in_sizes[0] / F;
    const int n_w     = in_sizes[1];
    const int E       = in_sizes[2];
    float* out = (float*)d_out;

    split_feat_kernel<<<(n_nodes * F + 255) / 256, 256>>>(feat, n_nodes * F);
    split_w_kernel<<<(n_w + 255) / 256, 256>>>(weight, n_w);

    cudaFuncSetAttribute(gemm_kernel,
                         cudaFuncAttributeMaxDynamicSharedMemorySize, SMEM_SZ);
    gemm_kernel<<<(n_nodes + 127) / 128, 512, SMEM_SZ>>>(n_nodes);

    cudaMemsetAsync(d_out, 0, (size_t)out_size * sizeof(float));
    scatter_kernel<<<(E + 7) / 8, 256>>>(src, dst, et, out, E, n_nodes);
}

// round 5
// speedup vs baseline: 1.8768x; 1.0875x over previous
#include <cuda_runtime.h>
#include <cuda_bf16.h>
#include <cstdint>

#define NREL 8
#define F    128
#define NMAX 100000
#define EMAX 1600000

// Scratch (no allocation allowed)
__device__ __align__(16) float         g_proj[(size_t)NREL * NMAX * F]; // 409.6 MB
__device__ __align__(16) __nv_bfloat16 g_fh[(size_t)NMAX * F];
__device__ __align__(16) __nv_bfloat16 g_fl[(size_t)NMAX * F];
__device__ __align__(16) __nv_bfloat16 g_wh[NREL * F * F];  // transposed: [r][n][k]
__device__ __align__(16) __nv_bfloat16 g_wl[NREL * F * F];  // transposed: [r][n][k]
// Counting-sort scratch
__device__ int g_cnt[NMAX + 1];
__device__ int g_off[NMAX + 1];
__device__ int g_cur[NMAX];
__device__ int g_eidx[EMAX];   // packed: src | (et << 17)

// ---------------------------------------------------------------------------
// fp32 -> bf16 hi/lo splits
// ---------------------------------------------------------------------------
__global__ void split_feat_kernel(const float* __restrict__ x, int n) {
    int i = blockIdx.x * blockDim.x + threadIdx.x;
    if (i < n) {
        float v = x[i];
        __nv_bfloat16 h = __float2bfloat16(v);
        g_fh[i] = h;
        g_fl[i] = __float2bfloat16(v - __bfloat162float(h));
    }
}

// weight [r][k][n] fp32 -> transposed bf16 hi/lo [r][n][k]
__global__ void split_w_kernel(const float* __restrict__ x, int n) {
    int i = blockIdx.x * blockDim.x + threadIdx.x;
    if (i < n) {
        int r = i >> 14, rem = i & 16383, k = rem >> 7, nn = rem & 127;
        float v = x[i];
        __nv_bfloat16 h = __float2bfloat16(v);
        int o = r * 16384 + nn * 128 + k;
        g_wh[o] = h;
        g_wl[o] = __float2bfloat16(v - __bfloat162float(h));
    }
}

// ---------------------------------------------------------------------------
// Counting sort by dst
// ---------------------------------------------------------------------------
__global__ void zero_cnt_kernel(int n) {
    int i = blockIdx.x * blockDim.x + threadIdx.x;
    if (i <= n) g_cnt[i] = 0;
}

__global__ void hist_kernel(const int* __restrict__ dst, int E) {
    int e = blockIdx.x * blockDim.x + threadIdx.x;
    if (e < E) atomicAdd(&g_cnt[dst[e]], 1);
}

// Single-block exclusive scan of g_cnt[0..n) -> g_off, g_cur; g_off[n] = total
__global__ void __launch_bounds__(1024) scan_kernel(int n) {
    const int tid = threadIdx.x, lane = tid & 31, wid = tid >> 5;
    __shared__ int wsum[32];
    __shared__ int base_s;
    if (tid == 0) base_s = 0;
    __syncthreads();
    for (int base = 0; base < n; base += 1024) {
        int i = base + tid;
        int x = (i < n) ? g_cnt[i] : 0;
        int v = x;
#pragma unroll
        for (int d = 1; d < 32; d <<= 1) {
            int t = __shfl_up_sync(0xFFFFFFFFu, v, d);
            if (lane >= d) v += t;
        }
        if (lane == 31) wsum[wid] = v;
        __syncthreads();
        if (wid == 0) {
            int s = wsum[lane];
            int sv = s;
#pragma unroll
            for (int d = 1; d < 32; d <<= 1) {
                int t = __shfl_up_sync(0xFFFFFFFFu, sv, d);
                if (lane >= d) sv += t;
            }
            wsum[lane] = sv - s;  // exclusive warp prefix
        }
        __syncthreads();
        int excl = base_s + wsum[wid] + v - x;
        if (i < n) { g_off[i] = excl; g_cur[i] = excl; }
        __syncthreads();
        if (tid == 1023) base_s += wsum[31] + v;  // chunk total
        __syncthreads();
    }
    if (tid == 0) g_off[n] = base_s;
}

__global__ void fill_kernel(const int* __restrict__ src,
                            const int* __restrict__ dst,
                            const int* __restrict__ et, int E) {
    int e = blockIdx.x * blockDim.x + threadIdx.x;
    if (e < E) {
        int p = atomicAdd(&g_cur[dst[e]], 1);
        g_eidx[p] = src[e] | (et[e] << 17);
    }
}

// ---------------------------------------------------------------------------
// Legacy-pipe GEMM building blocks
// ---------------------------------------------------------------------------
__device__ __forceinline__ uint32_t smem_u32(const void* p) {
    uint32_t a;
    asm("{ .reg .u64 t; cvta.to.shared.u64 t, %1; cvt.u32.u64 %0, t; }" : "=r"(a) : "l"(p));
    return a;
}

__device__ __forceinline__ void mma16816(float c[4], const uint32_t a[4],
                                         const uint32_t b0, const uint32_t b1) {
    asm volatile(
        "mma.sync.aligned.m16n8k16.row.col.f32.bf16.bf16.f32 "
        "{%0,%1,%2,%3}, {%4,%5,%6,%7}, {%8,%9}, {%0,%1,%2,%3};"
        : "+f"(c[0]), "+f"(c[1]), "+f"(c[2]), "+f"(c[3])
        : "r"(a[0]), "r"(a[1]), "r"(a[2]), "r"(a[3]), "r"(b0), "r"(b1));
}

#define LDSM_X4(r, addr) \
    asm volatile("ldmatrix.sync.aligned.m8n8.x4.shared.b16 {%0,%1,%2,%3}, [%4];" \
                 : "=r"((r)[0]), "=r"((r)[1]), "=r"((r)[2]), "=r"((r)[3]) : "r"(addr))

#define PITCH_B 272
#define TILE_SZ (128 * PITCH_B)   // 34816 B

__device__ __forceinline__ void cpa_tile(uint32_t s_base, const __nv_bfloat16* g,
                                         int valid_rows, int tid) {
    const char* gc = reinterpret_cast<const char*>(g);
#pragma unroll
    for (int it = 0; it < 4; it++) {
        int i = tid + it * 512;
        int m = i >> 4, c = i & 15;
        uint32_t s = s_base + m * PITCH_B + c * 16;
        const char* src = gc + m * 256 + c * 16;
        int sz = (m < valid_rows) ? 16 : 0;
        asm volatile("cp.async.cg.shared.global [%0], [%1], 16, %2;"
                     :: "r"(s), "l"(src), "r"(sz) : "memory");
    }
}

#define OFF_AH 0u
#define OFF_AL 34816u
#define OFF_B0 69632u
#define OFF_B1 139264u
#define SMEM_SZ 208896

__global__ void __launch_bounds__(512, 1) gemm_kernel(int n_nodes) {
    extern __shared__ __align__(128) char smem[];
    const uint32_t sb = smem_u32(smem);
    const int tid = threadIdx.x, wid = tid >> 5, lane = tid & 31;
    const int m0 = blockIdx.x * 128;
    const int valid = n_nodes - m0;

    cpa_tile(sb + OFF_AH, g_fh + (size_t)m0 * F, valid, tid);
    cpa_tile(sb + OFF_AL, g_fl + (size_t)m0 * F, valid, tid);
    cpa_tile(sb + OFF_B0,           g_wh, 128, tid);
    cpa_tile(sb + OFF_B0 + TILE_SZ, g_wl, 128, tid);
    asm volatile("cp.async.commit_group;" ::: "memory");
    asm volatile("cp.async.wait_group 0;" ::: "memory");
    __syncthreads();

    const int wm = (wid >> 1) * 16;
    const int wn = (wid & 1) * 64;

    const uint32_t a_off =
        (uint32_t)((wm + (lane & 15)) * PITCH_B + ((lane >> 4) * 8) * 2);
    const int b_row = (lane & 7) + ((lane >> 3) & 1) * 8;
    const uint32_t b_koff = (uint32_t)(((lane >> 4) * 8) * 2);

    const int r0 = wm + (lane >> 2);
    const bool ok0 = (m0 + r0) < n_nodes;
    const bool ok1 = (m0 + r0 + 8) < n_nodes;

    for (int q = 0; q < NREL; q++) {
        const uint32_t bb = sb + ((q & 1) ? OFF_B1 : OFF_B0);
        if (q < 7) {
            const uint32_t nb_ = sb + (((q + 1) & 1) ? OFF_B1 : OFF_B0);
            cpa_tile(nb_,           g_wh + (size_t)(q + 1) * F * F, 128, tid);
            cpa_tile(nb_ + TILE_SZ, g_wl + (size_t)(q + 1) * F * F, 128, tid);
            asm volatile("cp.async.commit_group;" ::: "memory");
        }

        float acc[8][4];
#pragma unroll
        for (int i = 0; i < 8; i++)
#pragma unroll
            for (int j = 0; j < 4; j++) acc[i][j] = 0.f;

#pragma unroll
        for (int kk = 0; kk < 8; kk++) {
            const uint32_t k2 = (uint32_t)(kk * 32);
            uint32_t ah[4], al[4];
            LDSM_X4(ah, sb + OFF_AH + a_off + k2);
            LDSM_X4(al, sb + OFF_AL + a_off + k2);
#pragma unroll
            for (int nb = 0; nb < 4; nb++) {
                const uint32_t baddr =
                    bb + (uint32_t)((wn + nb * 16 + b_row) * PITCH_B) + b_koff + k2;
                uint32_t bh[4], bl[4];
                LDSM_X4(bh, baddr);
                LDSM_X4(bl, baddr + TILE_SZ);
                float* a0 = acc[nb * 2];
                float* a1 = acc[nb * 2 + 1];
                mma16816(a0, ah, bh[0], bh[2]);
                mma16816(a1, ah, bh[1], bh[3]);
                mma16816(a0, al, bh[0], bh[2]);
                mma16816(a1, al, bh[1], bh[3]);
                mma16816(a0, ah, bl[0], bl[2]);
                mma16816(a1, ah, bl[1], bl[3]);
            }
        }

        float* cp = g_proj + ((size_t)q * n_nodes + m0) * F;
#pragma unroll
        for (int ns = 0; ns < 8; ns++) {
            const int col = wn + ns * 8 + (lane & 3) * 2;
            if (ok0) *(float2*)&cp[(size_t)r0 * F + col] =
                make_float2(acc[ns][0], acc[ns][1]);
            if (ok1) *(float2*)&cp[(size_t)(r0 + 8) * F + col] =
                make_float2(acc[ns][2], acc[ns][3]);
        }

        if (q < 7) {
            asm volatile("cp.async.wait_group 0;" ::: "memory");
            __syncthreads();
        }
    }
}

// ---------------------------------------------------------------------------
// Aggregation: one warp per dst node; register accumulation, no atomics.
// ---------------------------------------------------------------------------
__global__ void aggregate_kernel(float* __restrict__ out, int n_nodes) {
    int w = (blockIdx.x * blockDim.x + threadIdx.x) >> 5;
    int lane = threadIdx.x & 31;
    if (w >= n_nodes) return;
    int beg = g_off[w], end = g_off[w + 1];
    float4 acc = make_float4(0.f, 0.f, 0.f, 0.f);
    int j = beg;
    for (; j + 4 <= end; j += 4) {
        int v0 = g_eidx[j], v1 = g_eidx[j + 1];
        int v2 = g_eidx[j + 2], v3 = g_eidx[j + 3];
        const float4* p0 = reinterpret_cast<const float4*>(
            g_proj + ((size_t)(v0 >> 17) * n_nodes + (v0 & 0x1FFFF)) * F);
        const float4* p1 = reinterpret_cast<const float4*>(
            g_proj + ((size_t)(v1 >> 17) * n_nodes + (v1 & 0x1FFFF)) * F);
        const float4* p2 = reinterpret_cast<const float4*>(
            g_proj + ((size_t)(v2 >> 17) * n_nodes + (v2 & 0x1FFFF)) * F);
        const float4* p3 = reinterpret_cast<const float4*>(
            g_proj + ((size_t)(v3 >> 17) * n_nodes + (v3 & 0x1FFFF)) * F);
        float4 a = p0[lane], b = p1[lane], c = p2[lane], d = p3[lane];
        acc.x += (a.x + b.x) + (c.x + d.x);
        acc.y += (a.y + b.y) + (c.y + d.y);
        acc.z += (a.z + b.z) + (c.z + d.z);
        acc.w += (a.w + b.w) + (c.w + d.w);
    }
    for (; j < end; j++) {
        int v = g_eidx[j];
        const float4* p = reinterpret_cast<const float4*>(
            g_proj + ((size_t)(v >> 17) * n_nodes + (v & 0x1FFFF)) * F);
        float4 a = p[lane];
        acc.x += a.x; acc.y += a.y; acc.z += a.z; acc.w += a.w;
    }
    reinterpret_cast<float4*>(out + (size_t)w * F)[lane] = acc;
}

// ---------------------------------------------------------------------------
extern "C" void kernel_launch(void* const* d_in, const int* in_sizes, int n_in,
                              void* d_out, int out_size) {
    const float* feat   = (const float*)d_in[0];
    const float* weight = (const float*)d_in[1];
    const int*   src    = (const int*)d_in[2];
    const int*   dst    = (const int*)d_in[3];
    const int*   et     = (const int*)d_in[4];

    const int n_nodes = in_sizes[0] / F;
    const int n_w     = in_sizes[1];
    const int E       = in_sizes[2];
    float* out = (float*)d_out;

    // Counting sort by dst
    zero_cnt_kernel<<<(n_nodes + 256) / 256, 256>>>(n_nodes);
    hist_kernel<<<(E + 255) / 256, 256>>>(dst, E);
    scan_kernel<<<1, 1024>>>(n_nodes);
    fill_kernel<<<(E + 255) / 256, 256>>>(src, dst, et, E);

    // bf16 hi/lo splits
    split_feat_kernel<<<(n_nodes * F + 255) / 256, 256>>>(feat, n_nodes * F);
    split_w_kernel<<<(n_w + 255) / 256, 256>>>(weight, n_w);

    // Dense projections
    cudaFuncSetAttribute(gemm_kernel,
                         cudaFuncAttributeMaxDynamicSharedMemorySize, SMEM_SZ);
    gemm_kernel<<<(n_nodes + 127) / 128, 512, SMEM_SZ>>>(n_nodes);

    // Atomic-free segmented aggregation
    aggregate_kernel<<<(n_nodes * 32 + 255) / 256, 256>>>(out, n_nodes);
}

// round 6
// speedup vs baseline: 2.1782x; 1.1606x over previous
#include <cuda_runtime.h>
#include <cuda_fp16.h>
#include <cstdint>

#define NREL 8
#define F    128
#define NMAX 100000
#define EMAX 1600000

// Scratch (no allocation allowed)
__device__ __align__(16) float  g_proj[(size_t)NREL * NMAX * F]; // 409.6 MB
__device__ __align__(16) __half g_fh[(size_t)NMAX * F];
__device__ __align__(16) __half g_fl[(size_t)NMAX * F];
__device__ __align__(16) __half g_wh[NREL * F * F];  // transposed: [r][n][k], hi only
// Counting-sort scratch
__device__ int g_cnt[NMAX + 1];
__device__ int g_off[NMAX + 1];
__device__ int g_cur[NMAX];
__device__ int g_eidx[EMAX];   // packed: src | (et << 17)

// ---------------------------------------------------------------------------
// fp32 -> fp16 hi/lo split (feat); fp16 hi only (weights, transposed)
// ---------------------------------------------------------------------------
__global__ void split_feat_kernel(const float* __restrict__ x, int n) {
    int i = blockIdx.x * blockDim.x + threadIdx.x;
    if (i < n) {
        float v = x[i];
        __half h = __float2half_rn(v);
        g_fh[i] = h;
        g_fl[i] = __float2half_rn(v - __half2float(h));
    }
}

// weight [r][k][n] fp32 -> transposed fp16 [r][n][k]
__global__ void split_w_kernel(const float* __restrict__ x, int n) {
    int i = blockIdx.x * blockDim.x + threadIdx.x;
    if (i < n) {
        int r = i >> 14, rem = i & 16383, k = rem >> 7, nn = rem & 127;
        g_wh[r * 16384 + nn * 128 + k] = __float2half_rn(x[i]);
    }
}

// ---------------------------------------------------------------------------
// Counting sort by dst
// ---------------------------------------------------------------------------
__global__ void zero_cnt_kernel(int n) {
    int i = blockIdx.x * blockDim.x + threadIdx.x;
    if (i <= n) g_cnt[i] = 0;
}

__global__ void hist_kernel(const int* __restrict__ dst, int E) {
    int e = blockIdx.x * blockDim.x + threadIdx.x;
    if (e < E) atomicAdd(&g_cnt[dst[e]], 1);
}

// Single-block exclusive scan of g_cnt[0..n) -> g_off, g_cur; g_off[n] = total
__global__ void __launch_bounds__(1024) scan_kernel(int n) {
    const int tid = threadIdx.x, lane = tid & 31, wid = tid >> 5;
    __shared__ int wsum[32];
    __shared__ int base_s;
    if (tid == 0) base_s = 0;
    __syncthreads();
    for (int base = 0; base < n; base += 1024) {
        int i = base + tid;
        int x = (i < n) ? g_cnt[i] : 0;
        int v = x;
#pragma unroll
        for (int d = 1; d < 32; d <<= 1) {
            int t = __shfl_up_sync(0xFFFFFFFFu, v, d);
            if (lane >= d) v += t;
        }
        if (lane == 31) wsum[wid] = v;
        __syncthreads();
        if (wid == 0) {
            int s = wsum[lane];
            int sv = s;
#pragma unroll
            for (int d = 1; d < 32; d <<= 1) {
                int t = __shfl_up_sync(0xFFFFFFFFu, sv, d);
                if (lane >= d) sv += t;
            }
            wsum[lane] = sv - s;  // exclusive warp prefix
        }
        __syncthreads();
        int excl = base_s + wsum[wid] + v - x;
        if (i < n) { g_off[i] = excl; g_cur[i] = excl; }
        __syncthreads();
        if (tid == 1023) base_s += wsum[31] + v;  // chunk total
        __syncthreads();
    }
    if (tid == 0) g_off[n] = base_s;
}

__global__ void fill_kernel(const int* __restrict__ src,
                            const int* __restrict__ dst,
                            const int* __restrict__ et, int E) {
    int e = blockIdx.x * blockDim.x + threadIdx.x;
    if (e < E) {
        int p = atomicAdd(&g_cur[dst[e]], 1);
        g_eidx[p] = src[e] | (et[e] << 17);
    }
}

// ---------------------------------------------------------------------------
// Legacy-pipe GEMM building blocks
// ---------------------------------------------------------------------------
__device__ __forceinline__ uint32_t smem_u32(const void* p) {
    uint32_t a;
    asm("{ .reg .u64 t; cvta.to.shared.u64 t, %1; cvt.u32.u64 %0, t; }" : "=r"(a) : "l"(p));
    return a;
}

__device__ __forceinline__ void mma16816(float c[4], const uint32_t a[4],
                                         const uint32_t b0, const uint32_t b1) {
    asm volatile(
        "mma.sync.aligned.m16n8k16.row.col.f32.f16.f16.f32 "
        "{%0,%1,%2,%3}, {%4,%5,%6,%7}, {%8,%9}, {%0,%1,%2,%3};"
        : "+f"(c[0]), "+f"(c[1]), "+f"(c[2]), "+f"(c[3])
        : "r"(a[0]), "r"(a[1]), "r"(a[2]), "r"(a[3]), "r"(b0), "r"(b1));
}

#define LDSM_X4(r, addr) \
    asm volatile("ldmatrix.sync.aligned.m8n8.x4.shared.b16 {%0,%1,%2,%3}, [%4];" \
                 : "=r"((r)[0]), "=r"((r)[1]), "=r"((r)[2]), "=r"((r)[3]) : "r"(addr))

#define PITCH_B 272
#define TILE_SZ (128 * PITCH_B)   // 34816 B

__device__ __forceinline__ void cpa_tile(uint32_t s_base, const __half* g,
                                         int valid_rows, int tid) {
    const char* gc = reinterpret_cast<const char*>(g);
#pragma unroll
    for (int it = 0; it < 4; it++) {
        int i = tid + it * 512;
        int m = i >> 4, c = i & 15;
        uint32_t s = s_base + m * PITCH_B + c * 16;
        const char* src = gc + m * 256 + c * 16;
        int sz = (m < valid_rows) ? 16 : 0;
        asm volatile("cp.async.cg.shared.global [%0], [%1], 16, %2;"
                     :: "r"(s), "l"(src), "r"(sz) : "memory");
    }
}

// SMEM map: A-hi 0, A-lo 34816, B buf0 69632 (hi only), buf1 104448
#define OFF_AH 0u
#define OFF_AL 34816u
#define OFF_B0 69632u
#define OFF_B1 104448u
#define SMEM_SZ 139264

// ---------------------------------------------------------------------------
// GEMM: per CTA one 128-row M-tile, loop 8 relations.
// 512 threads = 16 warps (8 m-blocks x 2 n-halves), warp tile 16x64.
// 2-term fp16 split: (ah + al) * bh, fp32 accumulate.
// ---------------------------------------------------------------------------
__global__ void __launch_bounds__(512, 1) gemm_kernel(int n_nodes) {
    extern __shared__ __align__(128) char smem[];
    const uint32_t sb = smem_u32(smem);
    const int tid = threadIdx.x, wid = tid >> 5, lane = tid & 31;
    const int m0 = blockIdx.x * 128;
    const int valid = n_nodes - m0;

    cpa_tile(sb + OFF_AH, g_fh + (size_t)m0 * F, valid, tid);
    cpa_tile(sb + OFF_AL, g_fl + (size_t)m0 * F, valid, tid);
    cpa_tile(sb + OFF_B0, g_wh, 128, tid);
    asm volatile("cp.async.commit_group;" ::: "memory");
    asm volatile("cp.async.wait_group 0;" ::: "memory");
    __syncthreads();

    const int wm = (wid >> 1) * 16;
    const int wn = (wid & 1) * 64;

    const uint32_t a_off =
        (uint32_t)((wm + (lane & 15)) * PITCH_B + ((lane >> 4) * 8) * 2);
    const int b_row = (lane & 7) + ((lane >> 3) & 1) * 8;
    const uint32_t b_koff = (uint32_t)(((lane >> 4) * 8) * 2);

    const int r0 = wm + (lane >> 2);
    const bool ok0 = (m0 + r0) < n_nodes;
    const bool ok1 = (m0 + r0 + 8) < n_nodes;

    for (int q = 0; q < NREL; q++) {
        const uint32_t bb = sb + ((q & 1) ? OFF_B1 : OFF_B0);
        if (q < 7) {
            const uint32_t nb_ = sb + (((q + 1) & 1) ? OFF_B1 : OFF_B0);
            cpa_tile(nb_, g_wh + (size_t)(q + 1) * F * F, 128, tid);
            asm volatile("cp.async.commit_group;" ::: "memory");
        }

        float acc[8][4];
#pragma unroll
        for (int i = 0; i < 8; i++)
#pragma unroll
            for (int j = 0; j < 4; j++) acc[i][j] = 0.f;

#pragma unroll
        for (int kk = 0; kk < 8; kk++) {
            const uint32_t k2 = (uint32_t)(kk * 32);
            uint32_t ah[4], al[4];
            LDSM_X4(ah, sb + OFF_AH + a_off + k2);
            LDSM_X4(al, sb + OFF_AL + a_off + k2);
#pragma unroll
            for (int nb = 0; nb < 4; nb++) {
                const uint32_t baddr =
                    bb + (uint32_t)((wn + nb * 16 + b_row) * PITCH_B) + b_koff + k2;
                uint32_t bh[4];
                LDSM_X4(bh, baddr);
                float* a0 = acc[nb * 2];
                float* a1 = acc[nb * 2 + 1];
                mma16816(a0, ah, bh[0], bh[2]);
                mma16816(a1, ah, bh[1], bh[3]);
                mma16816(a0, al, bh[0], bh[2]);
                mma16816(a1, al, bh[1], bh[3]);
            }
        }

        float* cp = g_proj + ((size_t)q * n_nodes + m0) * F;
#pragma unroll
        for (int ns = 0; ns < 8; ns++) {
            const int col = wn + ns * 8 + (lane & 3) * 2;
            if (ok0) *(float2*)&cp[(size_t)r0 * F + col] =
                make_float2(acc[ns][0], acc[ns][1]);
            if (ok1) *(float2*)&cp[(size_t)(r0 + 8) * F + col] =
                make_float2(acc[ns][2], acc[ns][3]);
        }

        if (q < 7) {
            asm volatile("cp.async.wait_group 0;" ::: "memory");
            __syncthreads();
        }
    }
}

// ---------------------------------------------------------------------------
// Aggregation: one warp per dst node; register accumulation, no atomics.
// 8-wide unroll for MLP.
// ---------------------------------------------------------------------------
__global__ void aggregate_kernel(float* __restrict__ out, int n_nodes) {
    int w = (blockIdx.x * blockDim.x + threadIdx.x) >> 5;
    int lane = threadIdx.x & 31;
    if (w >= n_nodes) return;
    int beg = g_off[w], end = g_off[w + 1];
    float4 acc = make_float4(0.f, 0.f, 0.f, 0.f);
    int j = beg;
    for (; j + 8 <= end; j += 8) {
        const float4* p[8];
#pragma unroll
        for (int t = 0; t < 8; t++) {
            int v = g_eidx[j + t];
            p[t] = reinterpret_cast<const float4*>(
                g_proj + ((size_t)(v >> 17) * n_nodes + (v & 0x1FFFF)) * F);
        }
        float4 d0 = p[0][lane], d1 = p[1][lane], d2 = p[2][lane], d3 = p[3][lane];
        float4 d4 = p[4][lane], d5 = p[5][lane], d6 = p[6][lane], d7 = p[7][lane];
        acc.x += ((d0.x + d1.x) + (d2.x + d3.x)) + ((d4.x + d5.x) + (d6.x + d7.x));
        acc.y += ((d0.y + d1.y) + (d2.y + d3.y)) + ((d4.y + d5.y) + (d6.y + d7.y));
        acc.z += ((d0.z + d1.z) + (d2.z + d3.z)) + ((d4.z + d5.z) + (d6.z + d7.z));
        acc.w += ((d0.w + d1.w) + (d2.w + d3.w)) + ((d4.w + d5.w) + (d6.w + d7.w));
    }
    for (; j < end; j++) {
        int v = g_eidx[j];
        const float4* p = reinterpret_cast<const float4*>(
            g_proj + ((size_t)(v >> 17) * n_nodes + (v & 0x1FFFF)) * F);
        float4 a = p[lane];
        acc.x += a.x; acc.y += a.y; acc.z += a.z; acc.w += a.w;
    }
    reinterpret_cast<float4*>(out + (size_t)w * F)[lane] = acc;
}

// ---------------------------------------------------------------------------
extern "C" void kernel_launch(void* const* d_in, const int* in_sizes, int n_in,
                              void* d_out, int out_size) {
    const float* feat   = (const float*)d_in[0];
    const float* weight = (const float*)d_in[1];
    const int*   src    = (const int*)d_in[2];
    const int*   dst    = (const int*)d_in[3];
    const int*   et     = (const int*)d_in[4];

    const int n_nodes = in_sizes[0] / F;
    const int n_w     = in_sizes[1];
    const int E       = in_sizes[2];
    float* out = (float*)d_out;

    // Counting sort by dst
    zero_cnt_kernel<<<(n_nodes + 256) / 256, 256>>>(n_nodes);
    hist_kernel<<<(E + 255) / 256, 256>>>(dst, E);
    scan_kernel<<<1, 1024>>>(n_nodes);
    fill_kernel<<<(E + 255) / 256, 256>>>(src, dst, et, E);

    // fp16 splits
    split_feat_kernel<<<(n_nodes * F + 255) / 256, 256>>>(feat, n_nodes * F);
    split_w_kernel<<<(n_w + 255) / 256, 256>>>(weight, n_w);

    // Dense projections
    cudaFuncSetAttribute(gemm_kernel,
                         cudaFuncAttributeMaxDynamicSharedMemorySize, SMEM_SZ);
    gemm_kernel<<<(n_nodes + 127) / 128, 512, SMEM_SZ>>>(n_nodes);

    // Atomic-free segmented aggregation
    aggregate_kernel<<<(n_nodes * 32 + 255) / 256, 256>>>(out, n_nodes);
}

// round 7
// speedup vs baseline: 2.5259x; 1.1596x over previous
#include <cuda_runtime.h>
#include <cuda_fp16.h>
#include <cstdint>

#define NREL 8
#define F    128
#define NMAX 100000
#define EMAX 1600000
#define NBUCK (NMAX * NREL)

// Scratch (no allocation allowed)
__device__ __align__(16) __half g_Hh[(size_t)NREL * NMAX * F];  // 204.8 MB
__device__ __align__(16) __half g_Hl[(size_t)NREL * NMAX * F];  // 204.8 MB
__device__ __align__(16) __half g_wh[NREL * F * F];  // transposed: [r][n][k]
// (dst*8+et) counting-sort scratch
__device__ int g_cnt[NBUCK + 1];
__device__ int g_off[NBUCK + 1];
__device__ int g_cur[NBUCK];
__device__ int g_eidx[EMAX];   // src only (relation implied by segment)
__device__ int g_bsum[1024];

// ---------------------------------------------------------------------------
// weight [r][k][n] fp32 -> transposed fp16 [r][n][k] (hi only)
// ---------------------------------------------------------------------------
__global__ void split_w_kernel(const float* __restrict__ x, int n) {
    int i = blockIdx.x * blockDim.x + threadIdx.x;
    if (i < n) {
        int r = i >> 14, rem = i & 16383, k = rem >> 7, nn = rem & 127;
        g_wh[r * 16384 + nn * 128 + k] = __float2half_rn(x[i]);
    }
}

// ---------------------------------------------------------------------------
// Counting sort by key = dst*8 + et  (800K buckets, multi-block scan)
// ---------------------------------------------------------------------------
__global__ void zero_cnt_kernel(int nb) {
    int i = blockIdx.x * blockDim.x + threadIdx.x;
    if (i <= nb) g_cnt[i] = 0;
}

__global__ void hist_kernel(const int* __restrict__ dst,
                            const int* __restrict__ et, int E) {
    int e = blockIdx.x * blockDim.x + threadIdx.x;
    if (e < E) atomicAdd(&g_cnt[dst[e] * NREL + et[e]], 1);
}

// Pass 1: per-block (1024) exclusive scan; block totals -> g_bsum
__global__ void __launch_bounds__(1024) scan1_kernel(int n) {
    const int tid = threadIdx.x, lane = tid & 31, wid = tid >> 5;
    __shared__ int wsum[32];
    int i = blockIdx.x * 1024 + tid;
    int x = (i < n) ? g_cnt[i] : 0;
    int v = x;
#pragma unroll
    for (int d = 1; d < 32; d <<= 1) {
        int t = __shfl_up_sync(0xFFFFFFFFu, v, d);
        if (lane >= d) v += t;
    }
    if (lane == 31) wsum[wid] = v;
    __syncthreads();
    if (wid == 0) {
        int s = wsum[lane];
        int sv = s;
#pragma unroll
        for (int d = 1; d < 32; d <<= 1) {
            int t = __shfl_up_sync(0xFFFFFFFFu, sv, d);
            if (lane >= d) sv += t;
        }
        wsum[lane] = sv - s;  // exclusive warp prefix
    }
    __syncthreads();
    if (i < n) g_off[i] = wsum[wid] + v - x;   // block-local exclusive
    if (tid == 1023) g_bsum[blockIdx.x] = wsum[31] + v;  // block total
}

// Pass 2: single-block exclusive scan of the <=1024 block totals
__global__ void __launch_bounds__(1024) scan2_kernel(int nblk, int n) {
    const int tid = threadIdx.x, lane = tid & 31, wid = tid >> 5;
    __shared__ int wsum[32];
    int x = (tid < nblk) ? g_bsum[tid] : 0;
    int v = x;
#pragma unroll
    for (int d = 1; d < 32; d <<= 1) {
        int t = __shfl_up_sync(0xFFFFFFFFu, v, d);
        if (lane >= d) v += t;
    }
    if (lane == 31) wsum[wid] = v;
    __syncthreads();
    if (wid == 0) {
        int s = wsum[lane];
        int sv = s;
#pragma unroll
        for (int d = 1; d < 32; d <<= 1) {
            int t = __shfl_up_sync(0xFFFFFFFFu, sv, d);
            if (lane >= d) sv += t;
        }
        wsum[lane] = sv - s;
    }
    __syncthreads();
    if (tid < nblk) g_bsum[tid] = wsum[wid] + v - x;
    if (tid == 1023) g_off[n] = wsum[31] + v;   // grand total (= E)
}

// Pass 3: add block offsets; init cursors
__global__ void scan3_kernel(int n) {
    int i = blockIdx.x * blockDim.x + threadIdx.x;
    if (i < n) {
        int o = g_off[i] + g_bsum[i >> 10];
        g_off[i] = o;
        g_cur[i] = o;
    }
}

__global__ void fill_kernel(const int* __restrict__ src,
                            const int* __restrict__ dst,
                            const int* __restrict__ et, int E) {
    int e = blockIdx.x * blockDim.x + threadIdx.x;
    if (e < E) {
        int p = atomicAdd(&g_cur[dst[e] * NREL + et[e]], 1);
        g_eidx[p] = src[e];
    }
}

// ---------------------------------------------------------------------------
// Aggregate raw features: one warp per (dst, rel) segment. Gather feat rows
// (51 MB -> L2-resident), fp32 accumulate, fp16 hi/lo split, write H row.
// ---------------------------------------------------------------------------
__global__ void aggregate_kernel(const float* __restrict__ feat, int n_nodes) {
    int w = (blockIdx.x * blockDim.x + threadIdx.x) >> 5;
    int lane = threadIdx.x & 31;
    if (w >= n_nodes * NREL) return;
    int d = w >> 3, r = w & 7;
    int beg = g_off[w], end = g_off[w + 1];
    float4 acc = make_float4(0.f, 0.f, 0.f, 0.f);
    int j = beg;
    for (; j + 4 <= end; j += 4) {
        int s0 = g_eidx[j], s1 = g_eidx[j + 1];
        int s2 = g_eidx[j + 2], s3 = g_eidx[j + 3];
        float4 a = reinterpret_cast<const float4*>(feat + (size_t)s0 * F)[lane];
        float4 b = reinterpret_cast<const float4*>(feat + (size_t)s1 * F)[lane];
        float4 c = reinterpret_cast<const float4*>(feat + (size_t)s2 * F)[lane];
        float4 e = reinterpret_cast<const float4*>(feat + (size_t)s3 * F)[lane];
        acc.x += (a.x + b.x) + (c.x + e.x);
        acc.y += (a.y + b.y) + (c.y + e.y);
        acc.z += (a.z + b.z) + (c.z + e.z);
        acc.w += (a.w + b.w) + (c.w + e.w);
    }
    for (; j < end; j++) {
        int s = g_eidx[j];
        float4 a = reinterpret_cast<const float4*>(feat + (size_t)s * F)[lane];
        acc.x += a.x; acc.y += a.y; acc.z += a.z; acc.w += a.w;
    }
    // split fp32 -> fp16 hi + lo
    __half h0 = __float2half_rn(acc.x), h1 = __float2half_rn(acc.y);
    __half h2 = __float2half_rn(acc.z), h3 = __float2half_rn(acc.w);
    __half l0 = __float2half_rn(acc.x - __half2float(h0));
    __half l1 = __float2half_rn(acc.y - __half2float(h1));
    __half l2 = __float2half_rn(acc.z - __half2float(h2));
    __half l3 = __float2half_rn(acc.w - __half2float(h3));
    size_t ro = ((size_t)r * n_nodes + d) * F + lane * 4;
    __half2 a01 = __halves2half2(h0, h1), a23 = __halves2half2(h2, h3);
    __half2 b01 = __halves2half2(l0, l1), b23 = __halves2half2(l2, l3);
    uint2 uh, ul;
    uh.x = *reinterpret_cast<uint32_t*>(&a01);
    uh.y = *reinterpret_cast<uint32_t*>(&a23);
    ul.x = *reinterpret_cast<uint32_t*>(&b01);
    ul.y = *reinterpret_cast<uint32_t*>(&b23);
    *reinterpret_cast<uint2*>(g_Hh + ro) = uh;
    *reinterpret_cast<uint2*>(g_Hl + ro) = ul;
}

// ---------------------------------------------------------------------------
// Legacy-pipe GEMM building blocks
// ---------------------------------------------------------------------------
__device__ __forceinline__ uint32_t smem_u32(const void* p) {
    uint32_t a;
    asm("{ .reg .u64 t; cvta.to.shared.u64 t, %1; cvt.u32.u64 %0, t; }" : "=r"(a) : "l"(p));
    return a;
}

__device__ __forceinline__ void mma16816(float c[4], const uint32_t a[4],
                                         const uint32_t b0, const uint32_t b1) {
    asm volatile(
        "mma.sync.aligned.m16n8k16.row.col.f32.f16.f16.f32 "
        "{%0,%1,%2,%3}, {%4,%5,%6,%7}, {%8,%9}, {%0,%1,%2,%3};"
        : "+f"(c[0]), "+f"(c[1]), "+f"(c[2]), "+f"(c[3])
        : "r"(a[0]), "r"(a[1]), "r"(a[2]), "r"(a[3]), "r"(b0), "r"(b1));
}

#define LDSM_X4(r, addr) \
    asm volatile("ldmatrix.sync.aligned.m8n8.x4.shared.b16 {%0,%1,%2,%3}, [%4];" \
                 : "=r"((r)[0]), "=r"((r)[1]), "=r"((r)[2]), "=r"((r)[3]) : "r"(addr))

#define PITCH_B 272
#define TILE_SZ (128 * PITCH_B)   // 34816 B

__device__ __forceinline__ void cpa_tile(uint32_t s_base, const __half* g,
                                         int valid_rows, int tid) {
    const char* gc = reinterpret_cast<const char*>(g);
#pragma unroll
    for (int it = 0; it < 4; it++) {
        int i = tid + it * 512;
        int m = i >> 4, c = i & 15;
        uint32_t s = s_base + m * PITCH_B + c * 16;
        const char* src = gc + m * 256 + c * 16;
        int sz = (m < valid_rows) ? 16 : 0;
        asm volatile("cp.async.cg.shared.global [%0], [%1], 16, %2;"
                     :: "r"(s), "l"(src), "r"(sz) : "memory");
    }
}

// SMEM map: A(hi,lo) x2 buffers, B x2 buffers
#define OFF_AH0 0u
#define OFF_AL0 34816u
#define OFF_AH1 69632u
#define OFF_AL1 104448u
#define OFF_B0  139264u
#define OFF_B1  174080u
#define SMEM_SZ 208896

// ---------------------------------------------------------------------------
// GEMM: per CTA one 128-row dst tile; loop 8 relations with A=H_r (hi/lo),
// B=W_r hi; ACCUMULATE across relations in registers; write out once.
// ---------------------------------------------------------------------------
__global__ void __launch_bounds__(512, 1) gemm_kernel(float* __restrict__ out,
                                                      int n_nodes) {
    extern __shared__ __align__(128) char smem[];
    const uint32_t sb = smem_u32(smem);
    const int tid = threadIdx.x, wid = tid >> 5, lane = tid & 31;
    const int m0 = blockIdx.x * 128;
    const int valid = n_nodes - m0;

    // Prologue: relation 0 into buffer 0
    cpa_tile(sb + OFF_AH0, g_Hh + (size_t)m0 * F, valid, tid);
    cpa_tile(sb + OFF_AL0, g_Hl + (size_t)m0 * F, valid, tid);
    cpa_tile(sb + OFF_B0, g_wh, 128, tid);
    asm volatile("cp.async.commit_group;" ::: "memory");

    const int wm = (wid >> 1) * 16;
    const int wn = (wid & 1) * 64;
    const uint32_t a_off =
        (uint32_t)((wm + (lane & 15)) * PITCH_B + ((lane >> 4) * 8) * 2);
    const int b_row = (lane & 7) + ((lane >> 3) & 1) * 8;
    const uint32_t b_koff = (uint32_t)(((lane >> 4) * 8) * 2);

    float acc[8][4];
#pragma unroll
    for (int i = 0; i < 8; i++)
#pragma unroll
        for (int j = 0; j < 4; j++) acc[i][j] = 0.f;

    for (int q = 0; q < NREL; q++) {
        if (q < 7) {  // prefetch next relation into the other buffer
            const int nb1 = (q + 1) & 1;
            cpa_tile(sb + (nb1 ? OFF_AH1 : OFF_AH0),
                     g_Hh + ((size_t)(q + 1) * n_nodes + m0) * F, valid, tid);
            cpa_tile(sb + (nb1 ? OFF_AL1 : OFF_AL0),
                     g_Hl + ((size_t)(q + 1) * n_nodes + m0) * F, valid, tid);
            cpa_tile(sb + (nb1 ? OFF_B1 : OFF_B0),
                     g_wh + (size_t)(q + 1) * F * F, 128, tid);
            asm volatile("cp.async.commit_group;" ::: "memory");
            asm volatile("cp.async.wait_group 1;" ::: "memory");
        } else {
            asm volatile("cp.async.wait_group 0;" ::: "memory");
        }
        __syncthreads();

        const uint32_t ahb = sb + ((q & 1) ? OFF_AH1 : OFF_AH0);
        const uint32_t alb = sb + ((q & 1) ? OFF_AL1 : OFF_AL0);
        const uint32_t bb  = sb + ((q & 1) ? OFF_B1 : OFF_B0);

#pragma unroll
        for (int kk = 0; kk < 8; kk++) {
            const uint32_t k2 = (uint32_t)(kk * 32);
            uint32_t ah[4], al[4];
            LDSM_X4(ah, ahb + a_off + k2);
            LDSM_X4(al, alb + a_off + k2);
#pragma unroll
            for (int nb = 0; nb < 4; nb++) {
                const uint32_t baddr =
                    bb + (uint32_t)((wn + nb * 16 + b_row) * PITCH_B) + b_koff + k2;
                uint32_t bh[4];
                LDSM_X4(bh, baddr);
                float* a0 = acc[nb * 2];
                float* a1 = acc[nb * 2 + 1];
                mma16816(a0, ah, bh[0], bh[2]);
                mma16816(a1, ah, bh[1], bh[3]);
                mma16816(a0, al, bh[0], bh[2]);
                mma16816(a1, al, bh[1], bh[3]);
            }
        }
        __syncthreads();  // all warps done with buf (q&1) before it is refilled
    }

    // Epilogue: single write of the relation-summed tile
    const int r0 = wm + (lane >> 2);
    const bool ok0 = (m0 + r0) < n_nodes;
    const bool ok1 = (m0 + r0 + 8) < n_nodes;
    float* cp = out + (size_t)m0 * F;
#pragma unroll
    for (int ns = 0; ns < 8; ns++) {
        const int col = wn + ns * 8 + (lane & 3) * 2;
        if (ok0) *(float2*)&cp[(size_t)r0 * F + col] =
            make_float2(acc[ns][0], acc[ns][1]);
        if (ok1) *(float2*)&cp[(size_t)(r0 + 8) * F + col] =
            make_float2(acc[ns][2], acc[ns][3]);
    }
}

// ---------------------------------------------------------------------------
extern "C" void kernel_launch(void* const* d_in, const int* in_sizes, int n_in,
                              void* d_out, int out_size) {
    const float* feat   = (const float*)d_in[0];
    const float* weight = (const float*)d_in[1];
    const int*   src    = (const int*)d_in[2];
    const int*   dst    = (const int*)d_in[3];
    const int*   et     = (const int*)d_in[4];

    const int n_nodes = in_sizes[0] / F;
    const int n_w     = in_sizes[1];
    const int E       = in_sizes[2];
    float* out = (float*)d_out;

    const int nb = n_nodes * NREL;            // 800K buckets
    const int nblk = (nb + 1023) / 1024;      // scan blocks (<=1024)

    // Counting sort by (dst, et)
    zero_cnt_kernel<<<(nb + 256) / 256, 256>>>(nb);
    hist_kernel<<<(E + 255) / 256, 256>>>(dst, et, E);
    scan1_kernel<<<nblk, 1024>>>(nb);
    scan2_kernel<<<1, 1024>>>(nblk, nb);
    scan3_kernel<<<(nb + 255) / 256, 256>>>(nb);
    fill_kernel<<<(E + 255) / 256, 256>>>(src, dst, et, E);

    // Weights: fp16 hi, transposed
    split_w_kernel<<<(n_w + 255) / 256, 256>>>(weight, n_w);

    // Aggregate raw features into H[r][d] (fp16 hi/lo)
    aggregate_kernel<<<(nb * 32 + 255) / 256, 256>>>(feat, n_nodes);

    // Fused relation-sum GEMM: out = sum_r H_r @ W_r
    cudaFuncSetAttribute(gemm_kernel,
                         cudaFuncAttributeMaxDynamicSharedMemorySize, SMEM_SZ);
    gemm_kernel<<<(n_nodes + 127) / 128, 512, SMEM_SZ>>>(out, n_nodes);
}

// round 8
// speedup vs baseline: 3.3159x; 1.3128x over previous
#include <cuda_runtime.h>
#include <cuda_fp16.h>
#include <cstdint>

#define NREL 8
#define F    128
#define NMAX 100000
#define EMAX 1600000
#define NBUCK (NMAX * NREL)

// Scratch (no allocation allowed)
__device__ __align__(16) __half g_Hh[(size_t)NREL * NMAX * F];  // 204.8 MB
__device__ __align__(16) __half g_wh[NREL * F * F];  // transposed: [r][n][k]
// (dst*8+et) counting-sort scratch
__device__ int g_cnt[NBUCK + 1];
__device__ int g_off[NBUCK + 1];
__device__ int g_cur[NBUCK];
__device__ int g_eidx[EMAX];   // src only (relation implied by segment)
__device__ int g_bsum[1024];

// ---------------------------------------------------------------------------
// weight [r][k][n] fp32 -> transposed fp16 [r][n][k] (hi only)
// ---------------------------------------------------------------------------
__global__ void split_w_kernel(const float* __restrict__ x, int n) {
    int i = blockIdx.x * blockDim.x + threadIdx.x;
    if (i < n) {
        int r = i >> 14, rem = i & 16383, k = rem >> 7, nn = rem & 127;
        g_wh[r * 16384 + nn * 128 + k] = __float2half_rn(x[i]);
    }
}

// ---------------------------------------------------------------------------
// Counting sort by key = dst*8 + et  (800K buckets, multi-block scan)
// ---------------------------------------------------------------------------
__global__ void zero_cnt_kernel(int nb) {
    int i = blockIdx.x * blockDim.x + threadIdx.x;
    if (i <= nb) g_cnt[i] = 0;
}

__global__ void hist_kernel(const int* __restrict__ dst,
                            const int* __restrict__ et, int E) {
    int e = blockIdx.x * blockDim.x + threadIdx.x;
    if (e < E) atomicAdd(&g_cnt[dst[e] * NREL + et[e]], 1);
}

// Pass 1: per-block (1024) exclusive scan; block totals -> g_bsum
__global__ void __launch_bounds__(1024) scan1_kernel(int n) {
    const int tid = threadIdx.x, lane = tid & 31, wid = tid >> 5;
    __shared__ int wsum[32];
    int i = blockIdx.x * 1024 + tid;
    int x = (i < n) ? g_cnt[i] : 0;
    int v = x;
#pragma unroll
    for (int d = 1; d < 32; d <<= 1) {
        int t = __shfl_up_sync(0xFFFFFFFFu, v, d);
        if (lane >= d) v += t;
    }
    if (lane == 31) wsum[wid] = v;
    __syncthreads();
    if (wid == 0) {
        int s = wsum[lane];
        int sv = s;
#pragma unroll
        for (int d = 1; d < 32; d <<= 1) {
            int t = __shfl_up_sync(0xFFFFFFFFu, sv, d);
            if (lane >= d) sv += t;
        }
        wsum[lane] = sv - s;  // exclusive warp prefix
    }
    __syncthreads();
    if (i < n) g_off[i] = wsum[wid] + v - x;   // block-local exclusive
    if (tid == 1023) g_bsum[blockIdx.x] = wsum[31] + v;  // block total
}

// Pass 2: single-block exclusive scan of the <=1024 block totals
__global__ void __launch_bounds__(1024) scan2_kernel(int nblk, int n) {
    const int tid = threadIdx.x, lane = tid & 31, wid = tid >> 5;
    __shared__ int wsum[32];
    int x = (tid < nblk) ? g_bsum[tid] : 0;
    int v = x;
#pragma unroll
    for (int d = 1; d < 32; d <<= 1) {
        int t = __shfl_up_sync(0xFFFFFFFFu, v, d);
        if (lane >= d) v += t;
    }
    if (lane == 31) wsum[wid] = v;
    __syncthreads();
    if (wid == 0) {
        int s = wsum[lane];
        int sv = s;
#pragma unroll
        for (int d = 1; d < 32; d <<= 1) {
            int t = __shfl_up_sync(0xFFFFFFFFu, sv, d);
            if (lane >= d) sv += t;
        }
        wsum[lane] = sv - s;
    }
    __syncthreads();
    if (tid < nblk) g_bsum[tid] = wsum[wid] + v - x;
    if (tid == 1023) g_off[n] = wsum[31] + v;   // grand total (= E)
}

// Pass 3: add block offsets; init cursors
__global__ void scan3_kernel(int n) {
    int i = blockIdx.x * blockDim.x + threadIdx.x;
    if (i < n) {
        int o = g_off[i] + g_bsum[i >> 10];
        g_off[i] = o;
        g_cur[i] = o;
    }
}

__global__ void fill_kernel(const int* __restrict__ src,
                            const int* __restrict__ dst,
                            const int* __restrict__ et, int E) {
    int e = blockIdx.x * blockDim.x + threadIdx.x;
    if (e < E) {
        int p = atomicAdd(&g_cur[dst[e] * NREL + et[e]], 1);
        g_eidx[p] = src[e];
    }
}

// ---------------------------------------------------------------------------
// Aggregate raw features: one warp per (dst, rel) segment. Gather feat rows
// (51 MB -> L2-resident), fp32 accumulate, fp16 round, write H row (hi only).
// ---------------------------------------------------------------------------
__global__ void aggregate_kernel(const float* __restrict__ feat, int n_nodes) {
    int w = (blockIdx.x * blockDim.x + threadIdx.x) >> 5;
    int lane = threadIdx.x & 31;
    if (w >= n_nodes * NREL) return;
    int d = w >> 3, r = w & 7;
    int beg = g_off[w], end = g_off[w + 1];
    float4 acc = make_float4(0.f, 0.f, 0.f, 0.f);
    int j = beg;
    for (; j + 4 <= end; j += 4) {
        int s0 = g_eidx[j], s1 = g_eidx[j + 1];
        int s2 = g_eidx[j + 2], s3 = g_eidx[j + 3];
        float4 a = reinterpret_cast<const float4*>(feat + (size_t)s0 * F)[lane];
        float4 b = reinterpret_cast<const float4*>(feat + (size_t)s1 * F)[lane];
        float4 c = reinterpret_cast<const float4*>(feat + (size_t)s2 * F)[lane];
        float4 e = reinterpret_cast<const float4*>(feat + (size_t)s3 * F)[lane];
        acc.x += (a.x + b.x) + (c.x + e.x);
        acc.y += (a.y + b.y) + (c.y + e.y);
        acc.z += (a.z + b.z) + (c.z + e.z);
        acc.w += (a.w + b.w) + (c.w + e.w);
    }
    for (; j < end; j++) {
        int s = g_eidx[j];
        float4 a = reinterpret_cast<const float4*>(feat + (size_t)s * F)[lane];
        acc.x += a.x; acc.y += a.y; acc.z += a.z; acc.w += a.w;
    }
    __half2 a01 = __halves2half2(__float2half_rn(acc.x), __float2half_rn(acc.y));
    __half2 a23 = __halves2half2(__float2half_rn(acc.z), __float2half_rn(acc.w));
    uint2 uh;
    uh.x = *reinterpret_cast<uint32_t*>(&a01);
    uh.y = *reinterpret_cast<uint32_t*>(&a23);
    *reinterpret_cast<uint2*>(g_Hh + ((size_t)r * n_nodes + d) * F + lane * 4) = uh;
}

// ---------------------------------------------------------------------------
// Legacy-pipe GEMM building blocks
// ---------------------------------------------------------------------------
__device__ __forceinline__ uint32_t smem_u32(const void* p) {
    uint32_t a;
    asm("{ .reg .u64 t; cvta.to.shared.u64 t, %1; cvt.u32.u64 %0, t; }" : "=r"(a) : "l"(p));
    return a;
}

__device__ __forceinline__ void mma16816(float c[4], const uint32_t a[4],
                                         const uint32_t b0, const uint32_t b1) {
    asm volatile(
        "mma.sync.aligned.m16n8k16.row.col.f32.f16.f16.f32 "
        "{%0,%1,%2,%3}, {%4,%5,%6,%7}, {%8,%9}, {%0,%1,%2,%3};"
        : "+f"(c[0]), "+f"(c[1]), "+f"(c[2]), "+f"(c[3])
        : "r"(a[0]), "r"(a[1]), "r"(a[2]), "r"(a[3]), "r"(b0), "r"(b1));
}

#define LDSM_X4(r, addr) \
    asm volatile("ldmatrix.sync.aligned.m8n8.x4.shared.b16 {%0,%1,%2,%3}, [%4];" \
                 : "=r"((r)[0]), "=r"((r)[1]), "=r"((r)[2]), "=r"((r)[3]) : "r"(addr))

#define PITCH_B 272
#define TILE_SZ (128 * PITCH_B)   // 34816 B

__device__ __forceinline__ void cpa_tile(uint32_t s_base, const __half* g,
                                         int valid_rows, int tid) {
    const char* gc = reinterpret_cast<const char*>(g);
#pragma unroll
    for (int it = 0; it < 4; it++) {
        int i = tid + it * 512;
        int m = i >> 4, c = i & 15;
        uint32_t s = s_base + m * PITCH_B + c * 16;
        const char* src = gc + m * 256 + c * 16;
        int sz = (m < valid_rows) ? 16 : 0;
        asm volatile("cp.async.cg.shared.global [%0], [%1], 16, %2;"
                     :: "r"(s), "l"(src), "r"(sz) : "memory");
    }
}

// SMEM map: A x2 buffers, B x2 buffers
#define OFF_A0 0u
#define OFF_A1 34816u
#define OFF_B0 69632u
#define OFF_B1 104448u
#define SMEM_SZ 139264

// ---------------------------------------------------------------------------
// GEMM: per CTA one 128-row dst tile; loop 8 relations with A=H_r hi,
// B=W_r hi; ACCUMULATE across relations in registers; write out once.
// ---------------------------------------------------------------------------
__global__ void __launch_bounds__(512, 1) gemm_kernel(float* __restrict__ out,
                                                      int n_nodes) {
    extern __shared__ __align__(128) char smem[];
    const uint32_t sb = smem_u32(smem);
    const int tid = threadIdx.x, wid = tid >> 5, lane = tid & 31;
    const int m0 = blockIdx.x * 128;
    const int valid = n_nodes - m0;

    // Prologue: relation 0 into buffer 0
    cpa_tile(sb + OFF_A0, g_Hh + (size_t)m0 * F, valid, tid);
    cpa_tile(sb + OFF_B0, g_wh, 128, tid);
    asm volatile("cp.async.commit_group;" ::: "memory");

    const int wm = (wid >> 1) * 16;
    const int wn = (wid & 1) * 64;
    const uint32_t a_off =
        (uint32_t)((wm + (lane & 15)) * PITCH_B + ((lane >> 4) * 8) * 2);
    const int b_row = (lane & 7) + ((lane >> 3) & 1) * 8;
    const uint32_t b_koff = (uint32_t)(((lane >> 4) * 8) * 2);

    float acc[8][4];
#pragma unroll
    for (int i = 0; i < 8; i++)
#pragma unroll
        for (int j = 0; j < 4; j++) acc[i][j] = 0.f;

    for (int q = 0; q < NREL; q++) {
        if (q < 7) {  // prefetch next relation into the other buffer
            const int nb1 = (q + 1) & 1;
            cpa_tile(sb + (nb1 ? OFF_A1 : OFF_A0),
                     g_Hh + ((size_t)(q + 1) * n_nodes + m0) * F, valid, tid);
            cpa_tile(sb + (nb1 ? OFF_B1 : OFF_B0),
                     g_wh + (size_t)(q + 1) * F * F, 128, tid);
            asm volatile("cp.async.commit_group;" ::: "memory");
            asm volatile("cp.async.wait_group 1;" ::: "memory");
        } else {
            asm volatile("cp.async.wait_group 0;" ::: "memory");
        }
        __syncthreads();

        const uint32_t ab = sb + ((q & 1) ? OFF_A1 : OFF_A0);
        const uint32_t bb = sb + ((q & 1) ? OFF_B1 : OFF_B0);

#pragma unroll
        for (int kk = 0; kk < 8; kk++) {
            const uint32_t k2 = (uint32_t)(kk * 32);
            uint32_t ah[4];
            LDSM_X4(ah, ab + a_off + k2);
#pragma unroll
            for (int nb = 0; nb < 4; nb++) {
                const uint32_t baddr =
                    bb + (uint32_t)((wn + nb * 16 + b_row) * PITCH_B) + b_koff + k2;
                uint32_t bh[4];
                LDSM_X4(bh, baddr);
                mma16816(acc[nb * 2],     ah, bh[0], bh[2]);
                mma16816(acc[nb * 2 + 1], ah, bh[1], bh[3]);
            }
        }
        __syncthreads();  // all warps done with buf (q&1) before it is refilled
    }

    // Epilogue: single write of the relation-summed tile
    const int r0 = wm + (lane >> 2);
    const bool ok0 = (m0 + r0) < n_nodes;
    const bool ok1 = (m0 + r0 + 8) < n_nodes;
    float* cp = out + (size_t)m0 * F;
#pragma unroll
    for (int ns = 0; ns < 8; ns++) {
        const int col = wn + ns * 8 + (lane & 3) * 2;
        if (ok0) *(float2*)&cp[(size_t)r0 * F + col] =
            make_float2(acc[ns][0], acc[ns][1]);
        if (ok1) *(float2*)&cp[(size_t)(r0 + 8) * F + col] =
            make_float2(acc[ns][2], acc[ns][3]);
    }
}

// ---------------------------------------------------------------------------
extern "C" void kernel_launch(void* const* d_in, const int* in_sizes, int n_in,
                              void* d_out, int out_size) {
    const float* feat   = (const float*)d_in[0];
    const float* weight = (const float*)d_in[1];
    const int*   src    = (const int*)d_in[2];
    const int*   dst    = (const int*)d_in[3];
    const int*   et     = (const int*)d_in[4];

    const int n_nodes = in_sizes[0] / F;
    const int n_w     = in_sizes[1];
    const int E       = in_sizes[2];
    float* out = (float*)d_out;

    const int nb = n_nodes * NREL;            // 800K buckets
    const int nblk = (nb + 1023) / 1024;      // scan blocks (<=1024)

    // Counting sort by (dst, et)
    zero_cnt_kernel<<<(nb + 256) / 256, 256>>>(nb);
    hist_kernel<<<(E + 255) / 256, 256>>>(dst, et, E);
    scan1_kernel<<<nblk, 1024>>>(nb);
    scan2_kernel<<<1, 1024>>>(nblk, nb);
    scan3_kernel<<<(nb + 255) / 256, 256>>>(nb);
    fill_kernel<<<(E + 255) / 256, 256>>>(src, dst, et, E);

    // Weights: fp16 hi, transposed
    split_w_kernel<<<(n_w + 255) / 256, 256>>>(weight, n_w);

    // Aggregate raw features into H[r][d] (fp16)
    aggregate_kernel<<<(nb * 32 + 255) / 256, 256>>>(feat, n_nodes);

    // Fused relation-sum GEMM: out = sum_r H_r @ W_r
    cudaFuncSetAttribute(gemm_kernel,
                         cudaFuncAttributeMaxDynamicSharedMemorySize, SMEM_SZ);
    gemm_kernel<<<(n_nodes + 127) / 128, 512, SMEM_SZ>>>(out, n_nodes);
}